// round 4
// baseline (speedup 1.0000x reference)
#include <cuda_runtime.h>
#include <cuda_bf16.h>

#define MAXN 100000
#define MAXE 1600000
#define D    128
#define SCAN_BS 512
#define MAX_SCAN_BLOCKS 256

#define MT   128     // GEMM rows per block
#define AST  136     // A smem stride (bf16 elems) -> conflict-free frags
#define WST  136     // W smem stride

// ---------------- scratch (device globals; fully rewritten each launch) ----
__device__ __align__(16) float g_dis[MAXN];
__device__ __align__(16) float g_xw [(size_t)MAXN * D];   // current layer's x@W
__device__ __align__(16) float g_h  [(size_t)MAXN * D];   // conv1 output (relu'd)
__device__ int   g_cnt[MAXN];
__device__ int   g_incl[MAXN];
__device__ int   g_bsum[MAX_SCAN_BLOCKS];
__device__ int   g_rowstart[MAXN + 1];
__device__ int   g_cursor[MAXN];
__device__ __align__(8) int   g_csr_src[MAXE];
__device__ __align__(8) float g_csr_coef[MAXE];
__device__ int g_is64;                                    // edge dtype flag

// ---------------- edge dtype detection -------------------------------------
__global__ void k_detect(const int* __restrict__ e32, int nwords) {
    __shared__ int any;
    if (threadIdx.x == 0) any = 0;
    __syncthreads();
    int lim = nwords < 4096 ? nwords : 4096;
    for (int w = 1 + 2 * threadIdx.x; w < lim; w += 2 * blockDim.x)
        if (e32[w] != 0) any = 1;
    __syncthreads();
    if (threadIdx.x == 0) g_is64 = any ? 0 : 1;
}

__device__ __forceinline__ int edge_src(const int* e, int E, int i) {
    return g_is64 ? e[2 * (size_t)i] : e[i];
}
__device__ __forceinline__ int edge_dst(const int* e, int E, int i) {
    return g_is64 ? e[2 * ((size_t)E + i)] : e[(size_t)E + i];
}

// ---------------- CSR build -------------------------------------------------
__global__ void k_zero(int n) {
    int i = blockIdx.x * blockDim.x + threadIdx.x;
    if (i < n) { g_cnt[i] = 0; g_cursor[i] = 0; }
}

__global__ void k_hist(const int* __restrict__ edge, int E) {
    int i = blockIdx.x * blockDim.x + threadIdx.x;
    if (i < E) atomicAdd(&g_cnt[edge_dst(edge, E, i)], 1);
}

__global__ void k_dis(int n) {
    int i = blockIdx.x * blockDim.x + threadIdx.x;
    if (i < n) g_dis[i] = rsqrtf((float)g_cnt[i] + 1.0f);
}

__global__ void k_scan_block(int n) {
    __shared__ int sh[SCAN_BS];
    int i = blockIdx.x * SCAN_BS + threadIdx.x;
    int v = (i < n) ? g_cnt[i] : 0;
    sh[threadIdx.x] = v;
    __syncthreads();
    #pragma unroll
    for (int off = 1; off < SCAN_BS; off <<= 1) {
        int t = (threadIdx.x >= off) ? sh[threadIdx.x - off] : 0;
        __syncthreads();
        sh[threadIdx.x] += t;
        __syncthreads();
    }
    if (i < n) g_incl[i] = sh[threadIdx.x];
    if (threadIdx.x == SCAN_BS - 1) g_bsum[blockIdx.x] = sh[threadIdx.x];
}

__global__ void k_scan_tops(int nblocks) {
    __shared__ int sh[MAX_SCAN_BLOCKS];
    int v = (threadIdx.x < nblocks) ? g_bsum[threadIdx.x] : 0;
    sh[threadIdx.x] = v;
    __syncthreads();
    #pragma unroll
    for (int off = 1; off < MAX_SCAN_BLOCKS; off <<= 1) {
        int t = (threadIdx.x >= off) ? sh[threadIdx.x - off] : 0;
        __syncthreads();
        sh[threadIdx.x] += t;
        __syncthreads();
    }
    g_bsum[threadIdx.x] = sh[threadIdx.x] - v;  // exclusive
}

__global__ void k_scan_add(int n, int E) {
    int i = blockIdx.x * SCAN_BS + threadIdx.x;
    if (i < n) {
        int excl = g_incl[i] - g_cnt[i] + g_bsum[blockIdx.x];
        g_rowstart[i] = excl;
        if (i == n - 1) g_rowstart[n] = excl + g_cnt[i];
    }
}

__global__ void k_fill(const int* __restrict__ edge, int E) {
    int i = blockIdx.x * blockDim.x + threadIdx.x;
    if (i < E) {
        int s = edge_src(edge, E, i);
        int d = edge_dst(edge, E, i);
        int pos = g_rowstart[d] + atomicAdd(&g_cursor[d], 1);
        g_csr_src[pos]  = s;
        g_csr_coef[pos] = g_dis[s] * g_dis[d];
    }
}

// ---------------- bf16 helpers ---------------------------------------------
__device__ __forceinline__ unsigned pack_bf2(float x, float y) {
    unsigned lo = (unsigned)__bfloat16_as_ushort(__float2bfloat16_rn(x));
    unsigned hi = (unsigned)__bfloat16_as_ushort(__float2bfloat16_rn(y));
    return lo | (hi << 16);
}

__device__ __forceinline__ void mma16816(float* c, const unsigned* a, const unsigned* b) {
    asm volatile(
        "mma.sync.aligned.m16n8k16.row.col.f32.bf16.bf16.f32 "
        "{%0,%1,%2,%3},{%4,%5,%6,%7},{%8,%9},{%0,%1,%2,%3};"
        : "+f"(c[0]), "+f"(c[1]), "+f"(c[2]), "+f"(c[3])
        : "r"(a[0]), "r"(a[1]), "r"(a[2]), "r"(a[3]), "r"(b[0]), "r"(b[1]));
}

// ---------------- tensor-core GEMM (bf16 3-term split, fp32-grade) ---------
// out = f(A @ W + bias).  If W2 != null: second pass with same A tile.
// Block: 128 rows x 128 cols x K=128, 256 threads (8 warps of 32x64).
__global__ void __launch_bounds__(256, 1)
k_gemm_tc(const float* __restrict__ A, int n,
          const float* __restrict__ W1, const float* __restrict__ bias1, int relu1,
          float* __restrict__ out1,
          const float* __restrict__ W2, const float* __restrict__ bias2, int relu2,
          float* __restrict__ out2)
{
    extern __shared__ __align__(16) char smem[];
    __nv_bfloat16* Ah = (__nv_bfloat16*)smem;          // MT * AST
    __nv_bfloat16* Al = Ah + MT * AST;
    __nv_bfloat16* Wh = Al + MT * AST;                 // 128 * WST (n-major)
    __nv_bfloat16* Wl = Wh + 128 * WST;

    const int tid = threadIdx.x;
    const int rowBlock = blockIdx.x * MT;

    // ---- fill A (hi/lo), zero-pad OOB rows --------------------------------
    #pragma unroll
    for (int i = 0; i < 16; i++) {
        int idx = tid + i * 256;       // 0..4095 float4s (128 rows x 32)
        int r   = idx >> 5;
        int c   = (idx & 31) * 4;
        int grow = rowBlock + r;
        float4 v = make_float4(0.f, 0.f, 0.f, 0.f);
        if (grow < n) v = ((const float4*)(A + (size_t)grow * D))[idx & 31];
        float hx = __bfloat162float(__float2bfloat16_rn(v.x));
        float hy = __bfloat162float(__float2bfloat16_rn(v.y));
        float hz = __bfloat162float(__float2bfloat16_rn(v.z));
        float hw = __bfloat162float(__float2bfloat16_rn(v.w));
        unsigned* ph = (unsigned*)(Ah + r * AST + c);
        unsigned* pl = (unsigned*)(Al + r * AST + c);
        ph[0] = pack_bf2(hx, hy);          ph[1] = pack_bf2(hz, hw);
        pl[0] = pack_bf2(v.x - hx, v.y - hy); pl[1] = pack_bf2(v.z - hz, v.w - hw);
    }

    const int warp = tid >> 5, lane = tid & 31;
    const int wm = warp & 3;        // 0..3 -> rows wm*32
    const int wn = warp >> 2;       // 0..1 -> cols wn*64
    const int g  = lane >> 2, t = lane & 3;

    const int npass = W2 ? 2 : 1;
    for (int p = 0; p < npass; p++) {
        const float* W    = p ? W2    : W1;
        const float* bias = p ? bias2 : bias1;
        int          relu = p ? relu2 : relu1;
        float*       out  = p ? out2  : out1;

        if (p > 0) __syncthreads();   // previous pass done reading Wh/Wl
        // ---- fill W transposed (hi/lo): Wt[nn][k] = W[k][nn] --------------
        #pragma unroll
        for (int i = 0; i < 16; i++) {
            int idx = tid + i * 256;   // 0..4095 float4s (128 k-rows x 32)
            int k   = idx >> 5;
            int n0  = (idx & 31) * 4;
            float4 w = ((const float4*)(W + (size_t)k * D))[idx & 31];
            float ws[4] = {w.x, w.y, w.z, w.w};
            #pragma unroll
            for (int j = 0; j < 4; j++) {
                float hi = __bfloat162float(__float2bfloat16_rn(ws[j]));
                Wh[(n0 + j) * WST + k] = __float2bfloat16_rn(hi);
                Wl[(n0 + j) * WST + k] = __float2bfloat16_rn(ws[j] - hi);
            }
        }
        __syncthreads();

        // ---- compute ------------------------------------------------------
        float acc[2][8][4];
        #pragma unroll
        for (int mf = 0; mf < 2; mf++)
            #pragma unroll
            for (int nf = 0; nf < 8; nf++)
                #pragma unroll
                for (int c = 0; c < 4; c++) acc[mf][nf][c] = 0.f;

        #pragma unroll
        for (int ks = 0; ks < 8; ks++) {
            const int k0 = ks * 16;
            unsigned ah[2][4], al[2][4], bh[8][2];
            #pragma unroll
            for (int mf = 0; mf < 2; mf++) {
                int r0 = wm * 32 + mf * 16;
                ah[mf][0] = *(const unsigned*)(Ah + (r0 + g    ) * AST + k0 + 2 * t);
                ah[mf][1] = *(const unsigned*)(Ah + (r0 + g + 8) * AST + k0 + 2 * t);
                ah[mf][2] = *(const unsigned*)(Ah + (r0 + g    ) * AST + k0 + 2 * t + 8);
                ah[mf][3] = *(const unsigned*)(Ah + (r0 + g + 8) * AST + k0 + 2 * t + 8);
                al[mf][0] = *(const unsigned*)(Al + (r0 + g    ) * AST + k0 + 2 * t);
                al[mf][1] = *(const unsigned*)(Al + (r0 + g + 8) * AST + k0 + 2 * t);
                al[mf][2] = *(const unsigned*)(Al + (r0 + g    ) * AST + k0 + 2 * t + 8);
                al[mf][3] = *(const unsigned*)(Al + (r0 + g + 8) * AST + k0 + 2 * t + 8);
            }
            #pragma unroll
            for (int nf = 0; nf < 8; nf++) {
                int n0 = (wn * 64 + nf * 8 + g) * WST;
                bh[nf][0] = *(const unsigned*)(Wh + n0 + k0 + 2 * t);
                bh[nf][1] = *(const unsigned*)(Wh + n0 + k0 + 2 * t + 8);
            }
            // term1: Ah*Bh ; term3: Al*Bh  (Bh then dead)
            #pragma unroll
            for (int mf = 0; mf < 2; mf++)
                #pragma unroll
                for (int nf = 0; nf < 8; nf++) {
                    mma16816(acc[mf][nf], ah[mf], bh[nf]);
                    mma16816(acc[mf][nf], al[mf], bh[nf]);
                }
            // term2: Ah*Bl (reuse bh regs for Bl)
            #pragma unroll
            for (int nf = 0; nf < 8; nf++) {
                int n0 = (wn * 64 + nf * 8 + g) * WST;
                bh[nf][0] = *(const unsigned*)(Wl + n0 + k0 + 2 * t);
                bh[nf][1] = *(const unsigned*)(Wl + n0 + k0 + 2 * t + 8);
            }
            #pragma unroll
            for (int mf = 0; mf < 2; mf++)
                #pragma unroll
                for (int nf = 0; nf < 8; nf++)
                    mma16816(acc[mf][nf], ah[mf], bh[nf]);
        }

        // ---- epilogue -----------------------------------------------------
        #pragma unroll
        for (int mf = 0; mf < 2; mf++) {
            #pragma unroll
            for (int nf = 0; nf < 8; nf++) {
                int row = rowBlock + wm * 32 + mf * 16 + g;
                int col = wn * 64 + nf * 8 + 2 * t;
                float b0 = 0.f, b1 = 0.f;
                if (bias) { b0 = bias[col]; b1 = bias[col + 1]; }
                float2 v0, v1;
                v0.x = acc[mf][nf][0] + b0; v0.y = acc[mf][nf][1] + b1;
                v1.x = acc[mf][nf][2] + b0; v1.y = acc[mf][nf][3] + b1;
                if (relu) {
                    v0.x = fmaxf(v0.x, 0.f); v0.y = fmaxf(v0.y, 0.f);
                    v1.x = fmaxf(v1.x, 0.f); v1.y = fmaxf(v1.y, 0.f);
                }
                if (row < n)     *(float2*)(out + (size_t)row * D + col)       = v0;
                if (row + 8 < n) *(float2*)(out + (size_t)(row + 8) * D + col) = v1;
            }
        }
    }
}

// ---------------- CSR gather aggregation -----------------------------------
__global__ void k_gather(const float* __restrict__ xw,
                         float* __restrict__ out,
                         const float* __restrict__ bias, int relu,
                         int n)
{
    int warp = (blockIdx.x * blockDim.x + threadIdx.x) >> 5;
    int lane = threadIdx.x & 31;
    if (warp >= n) return;
    const int d = warp;

    float dis = g_dis[d];
    float dis2 = dis * dis;
    float4 self = ((const float4*)(xw + (size_t)d * D))[lane];
    float4 acc;
    acc.x = self.x * dis2; acc.y = self.y * dis2;
    acc.z = self.z * dis2; acc.w = self.w * dis2;

    int e   = g_rowstart[d];
    int end = g_rowstart[d + 1];

    for (; e + 1 < end; e += 2) {
        int   s0 = g_csr_src[e],  s1 = g_csr_src[e + 1];
        float c0 = g_csr_coef[e], c1 = g_csr_coef[e + 1];
        float4 v0 = ((const float4*)(xw + (size_t)s0 * D))[lane];
        float4 v1 = ((const float4*)(xw + (size_t)s1 * D))[lane];
        acc.x = fmaf(c0, v0.x, acc.x); acc.y = fmaf(c0, v0.y, acc.y);
        acc.z = fmaf(c0, v0.z, acc.z); acc.w = fmaf(c0, v0.w, acc.w);
        acc.x = fmaf(c1, v1.x, acc.x); acc.y = fmaf(c1, v1.y, acc.y);
        acc.z = fmaf(c1, v1.z, acc.z); acc.w = fmaf(c1, v1.w, acc.w);
    }
    if (e < end) {
        int   s0 = g_csr_src[e];
        float c0 = g_csr_coef[e];
        float4 v0 = ((const float4*)(xw + (size_t)s0 * D))[lane];
        acc.x = fmaf(c0, v0.x, acc.x); acc.y = fmaf(c0, v0.y, acc.y);
        acc.z = fmaf(c0, v0.z, acc.z); acc.w = fmaf(c0, v0.w, acc.w);
    }

    const int col = lane * 4;
    acc.x += bias[col]; acc.y += bias[col + 1];
    acc.z += bias[col + 2]; acc.w += bias[col + 3];
    if (relu) {
        acc.x = fmaxf(acc.x, 0.f); acc.y = fmaxf(acc.y, 0.f);
        acc.z = fmaxf(acc.z, 0.f); acc.w = fmaxf(acc.w, 0.f);
    }
    ((float4*)(out + (size_t)d * D))[lane] = acc;
}

// ---------------- launch ---------------------------------------------------
extern "C" void kernel_launch(void* const* d_in, const int* in_sizes, int n_in,
                              void* d_out, int out_size)
{
    const float* x    = (const float*)d_in[0];
    const int*   edge = (const int*)d_in[1];   // int32 or int64 (detected)
    const float* W1 = (const float*)d_in[2]; const float* b1 = (const float*)d_in[3];
    const float* W2 = (const float*)d_in[4]; const float* b2 = (const float*)d_in[5];
    const float* Wv = (const float*)d_in[6]; const float* bv = (const float*)d_in[7];
    const float* Wt = (const float*)d_in[8]; const float* bt = (const float*)d_in[9];

    const int n = in_sizes[0] / D;
    const int E = in_sizes[1] / 2;

    float* out_h = (float*)d_out;
    float* out_v = out_h + (size_t)n * D;
    float* out_t = out_v + (size_t)n * D;

    float* xw = nullptr; cudaGetSymbolAddress((void**)&xw, g_xw);
    float* h  = nullptr; cudaGetSymbolAddress((void**)&h,  g_h);

    const size_t SMEM = (size_t)(2 * MT * AST + 2 * 128 * WST) * sizeof(__nv_bfloat16);
    cudaFuncSetAttribute(k_gemm_tc, cudaFuncAttributeMaxDynamicSharedMemorySize, (int)SMEM);

    const int TB = 256;
    const int nscan = (n + SCAN_BS - 1) / SCAN_BS;

    // 0) dtype + CSR build + normalization
    k_detect<<<1, 512>>>(edge, 2 * E);
    k_zero<<<(n + TB - 1) / TB, TB>>>(n);
    k_hist<<<(E + TB - 1) / TB, TB>>>(edge, E);
    k_dis<<<(n + TB - 1) / TB, TB>>>(n);
    k_scan_block<<<nscan, SCAN_BS>>>(n);
    k_scan_tops<<<1, MAX_SCAN_BLOCKS>>>(nscan);
    k_scan_add<<<nscan, SCAN_BS>>>(n, E);
    k_fill<<<(E + TB - 1) / TB, TB>>>(edge, E);

    const int gemmGrid   = (n + MT - 1) / MT;
    const int gatherGrid = (n + 7) / 8;   // 8 warps / block

    // conv1: xw = x@W1 ; h = relu(agg + b1)
    k_gemm_tc<<<gemmGrid, TB, SMEM>>>(x, n, W1, nullptr, 0, xw,
                                      nullptr, nullptr, 0, nullptr);
    k_gather<<<gatherGrid, TB>>>(xw, h, b1, 1, n);
    // conv2: xw = h@W2 ; out_h = agg + b2
    k_gemm_tc<<<gemmGrid, TB, SMEM>>>(h, n, W2, nullptr, 0, xw,
                                      nullptr, nullptr, 0, nullptr);
    k_gather<<<gatherGrid, TB>>>(xw, out_h, b2, 0, n);
    // heads (dual pass, shared A tile)
    k_gemm_tc<<<gemmGrid, TB, SMEM>>>(out_h, n, Wv, bv, 1, out_v,
                                      Wt, bt, 1, out_t);
}

// round 6
// speedup vs baseline: 1.4876x; 1.4876x over previous
#include <cuda_runtime.h>

typedef unsigned long long u64;

#define MAXN 100000
#define MAXE 1600000
#define D    128
#define SCAN_BS 512
#define MAX_SCAN_BLOCKS 256

#define GT 64                        // GEMM rows per CTA
#define A_BYTES (GT * 128 * 8)       // As2: u64[GT][128] = 64KB
#define W_BYTES (128 * 128 * 4)      // Ws:  float[128][128] = 64KB

// ---------------- scratch (device globals; fully rewritten each launch) ----
__device__ __align__(16) float g_dis[MAXN];
__device__ __align__(16) float g_xw [(size_t)MAXN * D];
__device__ __align__(16) float g_h  [(size_t)MAXN * D];
__device__ int   g_cnt[MAXN];
__device__ int   g_incl[MAXN];
__device__ int   g_bsum[MAX_SCAN_BLOCKS];
__device__ int   g_rowstart[MAXN + 1];
__device__ int   g_cursor[MAXN];
__device__ __align__(8) int   g_csr_src[MAXE];
__device__ __align__(8) float g_csr_coef[MAXE];
__device__ int g_is64;

// ---------------- edge dtype detection -------------------------------------
__global__ void k_detect(const int* __restrict__ e32, int nwords) {
    __shared__ int any;
    if (threadIdx.x == 0) any = 0;
    __syncthreads();
    int lim = nwords < 4096 ? nwords : 4096;
    for (int w = 1 + 2 * threadIdx.x; w < lim; w += 2 * blockDim.x)
        if (e32[w] != 0) any = 1;
    __syncthreads();
    if (threadIdx.x == 0) g_is64 = any ? 0 : 1;
}
__device__ __forceinline__ int edge_src(const int* e, int E, int i) {
    return g_is64 ? e[2 * (size_t)i] : e[i];
}
__device__ __forceinline__ int edge_dst(const int* e, int E, int i) {
    return g_is64 ? e[2 * ((size_t)E + i)] : e[(size_t)E + i];
}

// ---------------- CSR build -------------------------------------------------
__global__ void k_zero(int n) {
    int i = blockIdx.x * blockDim.x + threadIdx.x;
    if (i < n) { g_cnt[i] = 0; g_cursor[i] = 0; }
}
// inclusive scan within blocks (also computes dis = rsqrt(deg+1))
__global__ void k_scan_block(int n) {
    __shared__ int sh[SCAN_BS];
    int i = blockIdx.x * SCAN_BS + threadIdx.x;
    int v = (i < n) ? g_cnt[i] : 0;
    if (i < n) g_dis[i] = rsqrtf((float)v + 1.0f);
    sh[threadIdx.x] = v;
    __syncthreads();
    #pragma unroll
    for (int off = 1; off < SCAN_BS; off <<= 1) {
        int t = (threadIdx.x >= off) ? sh[threadIdx.x - off] : 0;
        __syncthreads();
        sh[threadIdx.x] += t;
        __syncthreads();
    }
    if (i < n) g_incl[i] = sh[threadIdx.x];
    if (threadIdx.x == SCAN_BS - 1) g_bsum[blockIdx.x] = sh[threadIdx.x];
}
__global__ void k_scan_tops(int nblocks) {
    __shared__ int sh[MAX_SCAN_BLOCKS];
    int v = (threadIdx.x < nblocks) ? g_bsum[threadIdx.x] : 0;
    sh[threadIdx.x] = v;
    __syncthreads();
    #pragma unroll
    for (int off = 1; off < MAX_SCAN_BLOCKS; off <<= 1) {
        int t = (threadIdx.x >= off) ? sh[threadIdx.x - off] : 0;
        __syncthreads();
        sh[threadIdx.x] += t;
        __syncthreads();
    }
    g_bsum[threadIdx.x] = sh[threadIdx.x] - v;
}
__global__ void k_scan_add(int n, int E) {
    int i = blockIdx.x * SCAN_BS + threadIdx.x;
    if (i < n) {
        int excl = g_incl[i] - g_cnt[i] + g_bsum[blockIdx.x];
        g_rowstart[i] = excl;
        if (i == n - 1) g_rowstart[n] = excl + g_cnt[i];
    }
}
__global__ void k_fill(const int* __restrict__ edge, int E) {
    int i = blockIdx.x * blockDim.x + threadIdx.x;
    if (i < E) {
        int s = edge_src(edge, E, i);
        int d = edge_dst(edge, E, i);
        int pos = g_rowstart[d] + atomicAdd(&g_cursor[d], 1);
        g_csr_src[pos]  = s;
        g_csr_coef[pos] = g_dis[s] * g_dis[d];
    }
}

// ---------------- f32x2 helpers ---------------------------------------------
union F2U { float2 f; u64 u; };
__device__ __forceinline__ u64 dup_f32x2(float x) {
    F2U t; t.f = make_float2(x, x); return t.u;
}
__device__ __forceinline__ void ffma2(u64& acc, u64 a, u64 w) {
    asm("fma.rn.f32x2 %0, %1, %2, %0;" : "+l"(acc) : "l"(a), "l"(w));
}

// ---------------- packed-fp32 GEMM ------------------------------------------
// out1 = f(A @ W1 + bias1); if W2: out2 = f(A @ W2 + bias2) (same A tile).
// Exact fp32 math via fma.rn.f32x2 (2 MACs/issue on the FMA pipe).
// Block: GT=64 rows x 128 cols x K=128, 256 threads (warp w: rows w+8i).
// Optional: fold degree histogram (fire-and-forget REDs) into the launch.
__global__ void __launch_bounds__(256, 1)
k_gemm_f2(const float* __restrict__ A, int n,
          const float* __restrict__ W1, const float* __restrict__ bias1,
          int relu1, float* __restrict__ out1,
          const float* __restrict__ W2, const float* __restrict__ bias2,
          int relu2, float* __restrict__ out2,
          const int* __restrict__ edge, int E, int hist)
{
    extern __shared__ __align__(16) char smem[];
    u64*   As2 = (u64*)smem;                       // [GT][128] duplicated pairs
    float* Ws0 = (float*)(smem + A_BYTES);         // [128][128]
    float* Ws1 = (float*)(smem + A_BYTES + W_BYTES);

    const int tid = threadIdx.x;
    const int rowBlock = blockIdx.x * GT;

    // -- folded degree histogram (independent work, rides under FMA-bound) --
    if (hist) {
        int per  = (E + gridDim.x - 1) / gridDim.x;
        int base = blockIdx.x * per;
        int lim  = base + per; if (lim > E) lim = E;
        for (int i = base + tid; i < lim; i += 256)
            atomicAdd(&g_cnt[edge_dst(edge, E, i)], 1);
    }

    // -- fill A tile as duplicated f32x2 pairs ------------------------------
    #pragma unroll
    for (int i = 0; i < 8; i++) {
        int idx = tid + i * 256;           // 0..2047 float4s (64 rows x 32)
        int r   = idx >> 5;
        int c4  = idx & 31;
        int grow = rowBlock + r;
        float4 v = make_float4(0.f, 0.f, 0.f, 0.f);
        if (grow < n) v = ((const float4*)(A + (size_t)grow * D))[c4];
        u64* dst = As2 + r * 128 + c4 * 4;
        dst[0] = dup_f32x2(v.x); dst[1] = dup_f32x2(v.y);
        dst[2] = dup_f32x2(v.z); dst[3] = dup_f32x2(v.w);
    }
    // -- fill W tile(s) ------------------------------------------------------
    {
        const float4* W4 = (const float4*)W1;
        float4* d4 = (float4*)Ws0;
        #pragma unroll
        for (int i = 0; i < 16; i++) d4[tid + i * 256] = W4[tid + i * 256];
    }
    if (W2) {
        const float4* W4 = (const float4*)W2;
        float4* d4 = (float4*)Ws1;
        #pragma unroll
        for (int i = 0; i < 16; i++) d4[tid + i * 256] = W4[tid + i * 256];
    }
    __syncthreads();

    const int rg = tid >> 5;     // warp id -> rows rg + 8*ri
    const int cg = tid & 31;     // lane    -> cols 4*cg .. 4*cg+3

    const int npass = W2 ? 2 : 1;
    for (int p = 0; p < npass; p++) {
        const float* Ws   = p ? Ws1   : Ws0;
        const float* bias = p ? bias2 : bias1;
        int          relu = p ? relu2 : relu1;
        float*       out  = p ? out2  : out1;

        u64 acc[8][2];
        #pragma unroll
        for (int ri = 0; ri < 8; ri++) { acc[ri][0] = 0ull; acc[ri][1] = 0ull; }

        #pragma unroll 4
        for (int k = 0; k < 128; k++) {
            // two natural f32x2 pairs of W: (w[c],w[c+1]), (w[c+2],w[c+3])
            ulonglong2 w2 = *(const ulonglong2*)(Ws + k * 128 + cg * 4);
            #pragma unroll
            for (int ri = 0; ri < 8; ri++) {
                u64 a = As2[(rg + 8 * ri) * 128 + k];   // broadcast LDS.64
                ffma2(acc[ri][0], a, w2.x);
                ffma2(acc[ri][1], a, w2.y);
            }
        }

        // -- epilogue --------------------------------------------------------
        const int col = cg * 4;
        float b0 = 0.f, b1 = 0.f, b2 = 0.f, b3 = 0.f;
        if (bias) { b0 = bias[col]; b1 = bias[col+1]; b2 = bias[col+2]; b3 = bias[col+3]; }
        #pragma unroll
        for (int ri = 0; ri < 8; ri++) {
            int grow = rowBlock + rg + 8 * ri;
            if (grow >= n) continue;
            F2U lo, hi; lo.u = acc[ri][0]; hi.u = acc[ri][1];
            float4 o;
            o.x = lo.f.x + b0; o.y = lo.f.y + b1;
            o.z = hi.f.x + b2; o.w = hi.f.y + b3;
            if (relu) {
                o.x = fmaxf(o.x, 0.f); o.y = fmaxf(o.y, 0.f);
                o.z = fmaxf(o.z, 0.f); o.w = fmaxf(o.w, 0.f);
            }
            ((float4*)(out + (size_t)grow * D))[cg] = o;
        }
    }
}

// ---------------- CSR gather aggregation -----------------------------------
__global__ void k_gather(const float* __restrict__ xw,
                         float* __restrict__ out,
                         const float* __restrict__ bias, int relu,
                         int n)
{
    int warp = (blockIdx.x * blockDim.x + threadIdx.x) >> 5;
    int lane = threadIdx.x & 31;
    if (warp >= n) return;
    const int d = warp;

    float dis = g_dis[d];
    float dis2 = dis * dis;
    float4 self = ((const float4*)(xw + (size_t)d * D))[lane];
    float4 acc;
    acc.x = self.x * dis2; acc.y = self.y * dis2;
    acc.z = self.z * dis2; acc.w = self.w * dis2;

    int e   = g_rowstart[d];
    int end = g_rowstart[d + 1];

    for (; e + 1 < end; e += 2) {
        int   s0 = g_csr_src[e],  s1 = g_csr_src[e + 1];
        float c0 = g_csr_coef[e], c1 = g_csr_coef[e + 1];
        float4 v0 = ((const float4*)(xw + (size_t)s0 * D))[lane];
        float4 v1 = ((const float4*)(xw + (size_t)s1 * D))[lane];
        acc.x = fmaf(c0, v0.x, acc.x); acc.y = fmaf(c0, v0.y, acc.y);
        acc.z = fmaf(c0, v0.z, acc.z); acc.w = fmaf(c0, v0.w, acc.w);
        acc.x = fmaf(c1, v1.x, acc.x); acc.y = fmaf(c1, v1.y, acc.y);
        acc.z = fmaf(c1, v1.z, acc.z); acc.w = fmaf(c1, v1.w, acc.w);
    }
    if (e < end) {
        int   s0 = g_csr_src[e];
        float c0 = g_csr_coef[e];
        float4 v0 = ((const float4*)(xw + (size_t)s0 * D))[lane];
        acc.x = fmaf(c0, v0.x, acc.x); acc.y = fmaf(c0, v0.y, acc.y);
        acc.z = fmaf(c0, v0.z, acc.z); acc.w = fmaf(c0, v0.w, acc.w);
    }

    const int col = lane * 4;
    acc.x += bias[col]; acc.y += bias[col + 1];
    acc.z += bias[col + 2]; acc.w += bias[col + 3];
    if (relu) {
        acc.x = fmaxf(acc.x, 0.f); acc.y = fmaxf(acc.y, 0.f);
        acc.z = fmaxf(acc.z, 0.f); acc.w = fmaxf(acc.w, 0.f);
    }
    ((float4*)(out + (size_t)d * D))[lane] = acc;
}

// ---------------- launch ---------------------------------------------------
extern "C" void kernel_launch(void* const* d_in, const int* in_sizes, int n_in,
                              void* d_out, int out_size)
{
    const float* x    = (const float*)d_in[0];
    const int*   edge = (const int*)d_in[1];   // int32 or int64 (detected)
    const float* W1 = (const float*)d_in[2]; const float* b1 = (const float*)d_in[3];
    const float* W2 = (const float*)d_in[4]; const float* b2 = (const float*)d_in[5];
    const float* Wv = (const float*)d_in[6]; const float* bv = (const float*)d_in[7];
    const float* Wt = (const float*)d_in[8]; const float* bt = (const float*)d_in[9];

    const int n = in_sizes[0] / D;
    const int E = in_sizes[1] / 2;

    float* out_h = (float*)d_out;
    float* out_v = out_h + (size_t)n * D;
    float* out_t = out_v + (size_t)n * D;

    float* xw = nullptr; cudaGetSymbolAddress((void**)&xw, g_xw);
    float* h  = nullptr; cudaGetSymbolAddress((void**)&h,  g_h);

    const int SMEM1 = A_BYTES + W_BYTES;         // 128 KB
    const int SMEM2 = A_BYTES + 2 * W_BYTES;     // 192 KB (dual heads)
    cudaFuncSetAttribute(k_gemm_f2, cudaFuncAttributeMaxDynamicSharedMemorySize, SMEM2);

    const int TB = 256;
    const int nscan = (n + SCAN_BS - 1) / SCAN_BS;
    const int gemmGrid   = (n + GT - 1) / GT;
    const int gatherGrid = (n + 7) / 8;

    // dtype + zero, then conv1 GEMM with folded degree histogram
    k_detect<<<1, 512>>>(edge, 2 * E);
    k_zero<<<(n + TB - 1) / TB, TB>>>(n);
    k_gemm_f2<<<gemmGrid, TB, SMEM1>>>(x, n, W1, nullptr, 0, xw,
                                       nullptr, nullptr, 0, nullptr,
                                       edge, E, 1);
    // normalization + CSR
    k_scan_block<<<nscan, SCAN_BS>>>(n);
    k_scan_tops<<<1, MAX_SCAN_BLOCKS>>>(nscan);
    k_scan_add<<<nscan, SCAN_BS>>>(n, E);
    k_fill<<<(E + TB - 1) / TB, TB>>>(edge, E);
    // conv1 aggregate -> h
    k_gather<<<gatherGrid, TB>>>(xw, h, b1, 1, n);
    // conv2
    k_gemm_f2<<<gemmGrid, TB, SMEM1>>>(h, n, W2, nullptr, 0, xw,
                                       nullptr, nullptr, 0, nullptr,
                                       nullptr, 0, 0);
    k_gather<<<gatherGrid, TB>>>(xw, out_h, b2, 0, n);
    // heads (dual pass on one A tile)
    k_gemm_f2<<<gemmGrid, TB, SMEM2>>>(out_h, n, Wv, bv, 1, out_v,
                                       Wt, bt, 1, out_t,
                                       nullptr, 0, 0);
}